// round 1
// baseline (speedup 1.0000x reference)
#include <cuda_runtime.h>

#define BS 2
#define NN 2048
#define DIN 128
#define DOUT 128
#define H 8
#define DK 16

// -------- scratch (no allocs allowed) --------
__device__ float g_Q[(size_t)BS*H*NN*DK];
__device__ float g_K[(size_t)BS*H*NN*DK];
__device__ float g_V[(size_t)BS*H*NN*DK];

// ============================================================
// Projection: y = X @ W^T + b, written as [b][h][n][dk]
// grid (4096/64, 3), block 256
// ============================================================
#define PBM 64
__global__ __launch_bounds__(256) void proj_kernel(
    const float* __restrict__ X,
    const float* __restrict__ Wq, const float* __restrict__ bq,
    const float* __restrict__ Wk, const float* __restrict__ bk,
    const float* __restrict__ Wv, const float* __restrict__ bv)
{
    __shared__ float Xs[PBM][33];
    __shared__ float Wt[32][128];

    int tid = threadIdx.x;
    int sel = blockIdx.y;
    const float* W    = (sel == 0) ? Wq : ((sel == 1) ? Wk : Wv);
    const float* bias = (sel == 0) ? bq : ((sel == 1) ? bk : bv);
    float* dst        = (sel == 0) ? g_Q : ((sel == 1) ? g_K : g_V);

    int tx = tid & 63;      // cols tx and tx+64
    int ty = tid >> 6;      // 0..3 -> rows ty*16 .. ty*16+15
    int row0 = blockIdx.x * PBM;

    float acc0[16], acc1[16];
#pragma unroll
    for (int i = 0; i < 16; i++) { acc0[i] = 0.f; acc1[i] = 0.f; }

    for (int k0 = 0; k0 < DIN; k0 += 32) {
        __syncthreads();
        // stage X tile 64x32
#pragma unroll
        for (int r = 0; r < 2; r++) {
            int i = tid + 256 * r;          // float4 index 0..511
            int xr = i >> 3;
            int xc = (i & 7) << 2;
            float4 xv = *(const float4*)(X + (size_t)(row0 + xr) * DIN + k0 + xc);
            Xs[xr][xc + 0] = xv.x; Xs[xr][xc + 1] = xv.y;
            Xs[xr][xc + 2] = xv.z; Xs[xr][xc + 3] = xv.w;
        }
        // stage W^T tile 32x128
#pragma unroll
        for (int r = 0; r < 4; r++) {
            int i = tid + 256 * r;          // float4 index 0..1023
            int o  = i >> 3;
            int kc = (i & 7) << 2;
            float4 wv = *(const float4*)(W + (size_t)o * DIN + k0 + kc);
            Wt[kc + 0][o] = wv.x; Wt[kc + 1][o] = wv.y;
            Wt[kc + 2][o] = wv.z; Wt[kc + 3][o] = wv.w;
        }
        __syncthreads();
#pragma unroll
        for (int kk = 0; kk < 32; kk++) {
            float w0 = Wt[kk][tx];
            float w1 = Wt[kk][tx + 64];
#pragma unroll
            for (int rr = 0; rr < 16; rr++) {
                float xv = Xs[ty * 16 + rr][kk];
                acc0[rr] = fmaf(xv, w0, acc0[rr]);
                acc1[rr] = fmaf(xv, w1, acc1[rr]);
            }
        }
    }

    float b0 = bias[tx], b1 = bias[tx + 64];
    int c0 = tx, c1 = tx + 64;
#pragma unroll
    for (int rr = 0; rr < 16; rr++) {
        int grow = row0 + ty * 16 + rr;
        int b = grow / NN, n = grow % NN;
        dst[(((size_t)b * H + (c0 >> 4)) * NN + n) * DK + (c0 & 15)] = acc0[rr] + b0;
        dst[(((size_t)b * H + (c1 >> 4)) * NN + n) * DK + (c1 & 15)] = acc1[rr] + b1;
    }
}

// ============================================================
// Attention: one warp per query row.
// Per-lane m in {lane + 32*j, j=0..63}; scores resident in regs.
// k/v staged in smem tiles, row stride 20 floats (conflict-free LDS.128).
// grid (2048/8, 8, 2), block 256 (8 warps)
// ============================================================
#define TM 512
#define RT 8

__global__ __launch_bounds__(256, 2) void attn_kernel(
    const float* __restrict__ sp, const int* __restrict__ adj,
    float* __restrict__ outp, float* __restrict__ attnp)
{
    __shared__ float ts[TM * 20];

    int tid = threadIdx.x;
    int w = tid >> 5;
    int l = tid & 31;
    int h = blockIdx.y, b = blockIdx.z;
    int n = blockIdx.x * RT + w;
    int bh = b * H + h;

    const float* kb = g_K + (size_t)bh * NN * DK;
    const float* vb = g_V + (size_t)bh * NN * DK;
    const float* qrow = g_Q + ((size_t)bh * NN + n) * DK;

    // q pre-scaled by 1/sqrt(DK) = 0.25
    float q[DK];
#pragma unroll
    for (int d4 = 0; d4 < 4; d4++) {
        float4 t = *(const float4*)(qrow + d4 * 4);
        q[d4 * 4 + 0] = t.x * 0.25f; q[d4 * 4 + 1] = t.y * 0.25f;
        q[d4 * 4 + 2] = t.z * 0.25f; q[d4 * 4 + 3] = t.w * 0.25f;
    }

    const float* sprow  = sp + (size_t)n * NN;
    const int*   adjrow = adj + ((size_t)b * NN + n) * NN;

    float s[64];

    // ---------------- Pass 1: scores ----------------
#pragma unroll
    for (int t = 0; t < NN / TM; t++) {
        __syncthreads();
#pragma unroll
        for (int r = 0; r < 8; r++) {
            int i  = tid + 256 * r;           // float4 index 0..2047
            int mi = i >> 2;
            int d4 = (i & 3) << 2;
            float4 kv = *(const float4*)(kb + ((size_t)(t * TM + mi)) * DK + d4);
            *(float4*)(ts + mi * 20 + d4) = kv;
        }
        __syncthreads();
#pragma unroll
        for (int jj = 0; jj < TM / 32; jj++) {
            int lm = (jj << 5) + l;
            int m  = t * TM + lm;
            const float4* kr = (const float4*)(ts + lm * 20);
            float4 k0 = kr[0], k1 = kr[1], k2 = kr[2], k3 = kr[3];
            float d0 = q[0] * k0.x;  d0 = fmaf(q[1],  k0.y, d0);
            d0 = fmaf(q[2],  k0.z, d0); d0 = fmaf(q[3],  k0.w, d0);
            float d1 = q[4] * k1.x;  d1 = fmaf(q[5],  k1.y, d1);
            d1 = fmaf(q[6],  k1.z, d1); d1 = fmaf(q[7],  k1.w, d1);
            float d2 = q[8] * k2.x;  d2 = fmaf(q[9],  k2.y, d2);
            d2 = fmaf(q[10], k2.z, d2); d2 = fmaf(q[11], k2.w, d2);
            float d3 = q[12] * k3.x; d3 = fmaf(q[13], k3.y, d3);
            d3 = fmaf(q[14], k3.z, d3); d3 = fmaf(q[15], k3.w, d3);
            float dot = (d0 + d1) + (d2 + d3);
            float sv = sprow[m];
            if (m == n) sv = 0.f;
            float val = dot + sv;
            s[t * 16 + jj] = adjrow[m] ? val : -1e10f;
        }
    }

    // ---------------- Softmax (exact, register-resident) ----------------
    float mx = -3.0e38f;
#pragma unroll
    for (int j = 0; j < 64; j++) mx = fmaxf(mx, s[j]);
#pragma unroll
    for (int off = 16; off; off >>= 1)
        mx = fmaxf(mx, __shfl_xor_sync(0xffffffffu, mx, off));
    float sum = 0.f;
#pragma unroll
    for (int j = 0; j < 64; j++) { float e = __expf(s[j] - mx); s[j] = e; sum += e; }
#pragma unroll
    for (int off = 16; off; off >>= 1)
        sum += __shfl_xor_sync(0xffffffffu, sum, off);
    float inv = 1.f / sum;

    // ---------------- Pass 2: attn write + PV ----------------
    float o[DK];
#pragma unroll
    for (int d = 0; d < DK; d++) o[d] = 0.f;
    size_t arow = ((size_t)bh * NN + n) * NN;

#pragma unroll
    for (int t = 0; t < NN / TM; t++) {
        __syncthreads();
#pragma unroll
        for (int r = 0; r < 8; r++) {
            int i  = tid + 256 * r;
            int mi = i >> 2;
            int d4 = (i & 3) << 2;
            float4 vv = *(const float4*)(vb + ((size_t)(t * TM + mi)) * DK + d4);
            *(float4*)(ts + mi * 20 + d4) = vv;
        }
        __syncthreads();
#pragma unroll
        for (int jj = 0; jj < TM / 32; jj++) {
            int lm = (jj << 5) + l;
            int m  = t * TM + lm;
            float p = s[t * 16 + jj] * inv;
            if (attnp) attnp[arow + m] = p;
            const float4* vr = (const float4*)(ts + lm * 20);
            float4 v0 = vr[0], v1 = vr[1], v2 = vr[2], v3 = vr[3];
            o[0]  = fmaf(p, v0.x, o[0]);  o[1]  = fmaf(p, v0.y, o[1]);
            o[2]  = fmaf(p, v0.z, o[2]);  o[3]  = fmaf(p, v0.w, o[3]);
            o[4]  = fmaf(p, v1.x, o[4]);  o[5]  = fmaf(p, v1.y, o[5]);
            o[6]  = fmaf(p, v1.z, o[6]);  o[7]  = fmaf(p, v1.w, o[7]);
            o[8]  = fmaf(p, v2.x, o[8]);  o[9]  = fmaf(p, v2.y, o[9]);
            o[10] = fmaf(p, v2.z, o[10]); o[11] = fmaf(p, v2.w, o[11]);
            o[12] = fmaf(p, v3.x, o[12]); o[13] = fmaf(p, v3.y, o[13]);
            o[14] = fmaf(p, v3.z, o[14]); o[15] = fmaf(p, v3.w, o[15]);
        }
    }

    // warp butterfly reduce PV partials
#pragma unroll
    for (int off = 16; off; off >>= 1) {
#pragma unroll
        for (int d = 0; d < DK; d++)
            o[d] += __shfl_xor_sync(0xffffffffu, o[d], off);
    }

    // out layout: (b, n, dk, h) flattened -> out[(b*N+n)*128 + d*8 + h]
    if (outp && l == 0) {
        float* ob = outp + ((size_t)b * NN + n) * DOUT + h;
#pragma unroll
        for (int d = 0; d < DK; d++) ob[(size_t)d * H] = o[d];
    }
}

// ============================================================
extern "C" void kernel_launch(void* const* d_in, const int* in_sizes, int n_in,
                              void* d_out, int out_size) {
    const float* x   = (const float*)d_in[0];
    const int*   adj = (const int*)  d_in[1];
    const float* sp  = (const float*)d_in[2];
    const float* Wq  = (const float*)d_in[3];
    const float* bq  = (const float*)d_in[4];
    const float* Wk  = (const float*)d_in[5];
    const float* bk  = (const float*)d_in[6];
    const float* Wv  = (const float*)d_in[7];
    const float* bv  = (const float*)d_in[8];

    const long long OUT_ELEMS  = (long long)BS * NN * DOUT;            // 524288
    const long long ATTN_ELEMS = (long long)BS * H * NN * (long long)NN; // 67108864

    float* base  = (float*)d_out;
    float* outp  = nullptr;
    float* attnp = nullptr;
    long long osz = (long long)out_size;
    if (osz >= OUT_ELEMS + ATTN_ELEMS) { outp = base; attnp = base + OUT_ELEMS; }
    else if (osz == ATTN_ELEMS)        { attnp = base; }
    else                               { outp = base; }

    dim3 pgrid(BS * NN / PBM, 3);
    proj_kernel<<<pgrid, 256>>>(x, Wq, bq, Wk, bk, Wv, bv);

    dim3 agrid(NN / RT, H, BS);
    attn_kernel<<<agrid, 256>>>(sp, adj, outp, attnp);
}

// round 2
// speedup vs baseline: 1.1021x; 1.1021x over previous
#include <cuda_runtime.h>

#define BS 2
#define NN 2048
#define DIN 128
#define DOUT 128
#define H 8
#define DK 16

// -------- scratch (no allocs allowed) --------
__device__ float g_Q[(size_t)BS*H*NN*DK];
__device__ float g_K[(size_t)BS*H*NN*DK];
__device__ float g_V[(size_t)BS*H*NN*DK];

// ============================================================
// Projection: y = X @ W^T + b, written as [b][h][n][dk]
// grid (4096/64, 3), block 256
// ============================================================
#define PBM 64
__global__ __launch_bounds__(256) void proj_kernel(
    const float* __restrict__ X,
    const float* __restrict__ Wq, const float* __restrict__ bq,
    const float* __restrict__ Wk, const float* __restrict__ bk,
    const float* __restrict__ Wv, const float* __restrict__ bv)
{
    __shared__ float Xs[PBM][33];
    __shared__ float Wt[32][128];

    int tid = threadIdx.x;
    int sel = blockIdx.y;
    const float* W    = (sel == 0) ? Wq : ((sel == 1) ? Wk : Wv);
    const float* bias = (sel == 0) ? bq : ((sel == 1) ? bk : bv);
    float* dst        = (sel == 0) ? g_Q : ((sel == 1) ? g_K : g_V);

    int tx = tid & 63;      // cols tx and tx+64
    int ty = tid >> 6;      // 0..3 -> rows ty*16 .. ty*16+15
    int row0 = blockIdx.x * PBM;

    float acc0[16], acc1[16];
#pragma unroll
    for (int i = 0; i < 16; i++) { acc0[i] = 0.f; acc1[i] = 0.f; }

    for (int k0 = 0; k0 < DIN; k0 += 32) {
        __syncthreads();
#pragma unroll
        for (int r = 0; r < 2; r++) {
            int i = tid + 256 * r;
            int xr = i >> 3;
            int xc = (i & 7) << 2;
            float4 xv = *(const float4*)(X + (size_t)(row0 + xr) * DIN + k0 + xc);
            Xs[xr][xc + 0] = xv.x; Xs[xr][xc + 1] = xv.y;
            Xs[xr][xc + 2] = xv.z; Xs[xr][xc + 3] = xv.w;
        }
#pragma unroll
        for (int r = 0; r < 4; r++) {
            int i = tid + 256 * r;
            int o  = i >> 3;
            int kc = (i & 7) << 2;
            float4 wv = *(const float4*)(W + (size_t)o * DIN + k0 + kc);
            Wt[kc + 0][o] = wv.x; Wt[kc + 1][o] = wv.y;
            Wt[kc + 2][o] = wv.z; Wt[kc + 3][o] = wv.w;
        }
        __syncthreads();
#pragma unroll
        for (int kk = 0; kk < 32; kk++) {
            float w0 = Wt[kk][tx];
            float w1 = Wt[kk][tx + 64];
#pragma unroll
            for (int rr = 0; rr < 16; rr++) {
                float xv = Xs[ty * 16 + rr][kk];
                acc0[rr] = fmaf(xv, w0, acc0[rr]);
                acc1[rr] = fmaf(xv, w1, acc1[rr]);
            }
        }
    }

    float b0 = bias[tx], b1 = bias[tx + 64];
    int c0 = tx, c1 = tx + 64;
#pragma unroll
    for (int rr = 0; rr < 16; rr++) {
        int grow = row0 + ty * 16 + rr;
        int b = grow / NN, n = grow % NN;
        dst[(((size_t)b * H + (c0 >> 4)) * NN + n) * DK + (c0 & 15)] = acc0[rr] + b0;
        dst[(((size_t)b * H + (c1 >> 4)) * NN + n) * DK + (c1 & 15)] = acc1[rr] + b1;
    }
}

// ============================================================
// Attention: one warp per TWO query rows (amortizes K/V smem reads).
// Per-lane m in {lane + 32*j}; scores for both rows resident in regs.
// k/v staged in smem tiles, row stride 20 floats (conflict-free LDS.128).
// grid (2048/16, 8, 2), block 256 (8 warps, 16 rows)
// ============================================================
#define TM 512
#define RT 16
#define NTILE (NN / TM)     // 4
#define SJ (TM / 32)        // 16 score regs per tile per row

__global__ __launch_bounds__(256, 1) void attn_kernel(
    const float* __restrict__ sp, const int* __restrict__ adj,
    float* __restrict__ outp, float* __restrict__ attnp)
{
    __shared__ float ts[TM * 20];

    int tid = threadIdx.x;
    int w = tid >> 5;
    int l = tid & 31;
    int h = blockIdx.y, b = blockIdx.z;
    int n0 = blockIdx.x * RT + w * 2;   // rows n0, n0+1
    int n1 = n0 + 1;
    int bh = b * H + h;

    const float* kb = g_K + (size_t)bh * NN * DK;
    const float* vb = g_V + (size_t)bh * NN * DK;

    // q pre-scaled by 1/sqrt(DK) = 0.25
    float qa[DK], qb2[DK];
    {
        const float* qr0 = g_Q + ((size_t)bh * NN + n0) * DK;
        const float* qr1 = g_Q + ((size_t)bh * NN + n1) * DK;
#pragma unroll
        for (int d4 = 0; d4 < 4; d4++) {
            float4 t0 = *(const float4*)(qr0 + d4 * 4);
            float4 t1 = *(const float4*)(qr1 + d4 * 4);
            qa[d4*4+0] = t0.x*0.25f; qa[d4*4+1] = t0.y*0.25f;
            qa[d4*4+2] = t0.z*0.25f; qa[d4*4+3] = t0.w*0.25f;
            qb2[d4*4+0] = t1.x*0.25f; qb2[d4*4+1] = t1.y*0.25f;
            qb2[d4*4+2] = t1.z*0.25f; qb2[d4*4+3] = t1.w*0.25f;
        }
    }

    const float* sp0  = sp + (size_t)n0 * NN;
    const float* sp1  = sp + (size_t)n1 * NN;
    const int*   adj0 = adj + ((size_t)b * NN + n0) * NN;
    const int*   adj1 = adj + ((size_t)b * NN + n1) * NN;

    float s0[64], s1[64];

    // ---------------- Pass 1: scores ----------------
#pragma unroll
    for (int t = 0; t < NTILE; t++) {
        __syncthreads();
#pragma unroll
        for (int r = 0; r < 8; r++) {
            int i  = tid + 256 * r;
            int mi = i >> 2;
            int d4 = (i & 3) << 2;
            float4 kv = *(const float4*)(kb + ((size_t)(t * TM + mi)) * DK + d4);
            *(float4*)(ts + mi * 20 + d4) = kv;
        }
        __syncthreads();
#pragma unroll
        for (int jj = 0; jj < SJ; jj++) {
            int lm = (jj << 5) + l;
            int m  = t * TM + lm;
            const float4* kr = (const float4*)(ts + lm * 20);
            float4 k0 = kr[0], k1 = kr[1], k2 = kr[2], k3 = kr[3];

            float a0 = qa[0]*k0.x;  a0 = fmaf(qa[1],k0.y,a0);
            a0 = fmaf(qa[2],k0.z,a0); a0 = fmaf(qa[3],k0.w,a0);
            float a1 = qa[4]*k1.x;  a1 = fmaf(qa[5],k1.y,a1);
            a1 = fmaf(qa[6],k1.z,a1); a1 = fmaf(qa[7],k1.w,a1);
            float a2 = qa[8]*k2.x;  a2 = fmaf(qa[9],k2.y,a2);
            a2 = fmaf(qa[10],k2.z,a2); a2 = fmaf(qa[11],k2.w,a2);
            float a3 = qa[12]*k3.x; a3 = fmaf(qa[13],k3.y,a3);
            a3 = fmaf(qa[14],k3.z,a3); a3 = fmaf(qa[15],k3.w,a3);
            float dotA = (a0 + a1) + (a2 + a3);

            float c0 = qb2[0]*k0.x;  c0 = fmaf(qb2[1],k0.y,c0);
            c0 = fmaf(qb2[2],k0.z,c0); c0 = fmaf(qb2[3],k0.w,c0);
            float c1 = qb2[4]*k1.x;  c1 = fmaf(qb2[5],k1.y,c1);
            c1 = fmaf(qb2[6],k1.z,c1); c1 = fmaf(qb2[7],k1.w,c1);
            float c2 = qb2[8]*k2.x;  c2 = fmaf(qb2[9],k2.y,c2);
            c2 = fmaf(qb2[10],k2.z,c2); c2 = fmaf(qb2[11],k2.w,c2);
            float c3 = qb2[12]*k3.x; c3 = fmaf(qb2[13],k3.y,c3);
            c3 = fmaf(qb2[14],k3.z,c3); c3 = fmaf(qb2[15],k3.w,c3);
            float dotB = (c0 + c1) + (c2 + c3);

            float sv0 = sp0[m]; if (m == n0) sv0 = 0.f;
            float sv1 = sp1[m]; if (m == n1) sv1 = 0.f;
            s0[t * SJ + jj] = adj0[m] ? (dotA + sv0) : -1e10f;
            s1[t * SJ + jj] = adj1[m] ? (dotB + sv1) : -1e10f;
        }
    }

    // ---------------- Softmax (exact, register-resident) ----------------
    float mx0 = -3.0e38f, mx1 = -3.0e38f;
#pragma unroll
    for (int j = 0; j < 64; j++) { mx0 = fmaxf(mx0, s0[j]); mx1 = fmaxf(mx1, s1[j]); }
#pragma unroll
    for (int off = 16; off; off >>= 1) {
        mx0 = fmaxf(mx0, __shfl_xor_sync(0xffffffffu, mx0, off));
        mx1 = fmaxf(mx1, __shfl_xor_sync(0xffffffffu, mx1, off));
    }
    float sum0 = 0.f, sum1 = 0.f;
#pragma unroll
    for (int j = 0; j < 64; j++) {
        float e0 = __expf(s0[j] - mx0); s0[j] = e0; sum0 += e0;
        float e1 = __expf(s1[j] - mx1); s1[j] = e1; sum1 += e1;
    }
#pragma unroll
    for (int off = 16; off; off >>= 1) {
        sum0 += __shfl_xor_sync(0xffffffffu, sum0, off);
        sum1 += __shfl_xor_sync(0xffffffffu, sum1, off);
    }
    float inv0 = 1.f / sum0, inv1 = 1.f / sum1;

    // ---------------- Pass 2: attn write + PV ----------------
    float o0[DK], o1[DK];
#pragma unroll
    for (int d = 0; d < DK; d++) { o0[d] = 0.f; o1[d] = 0.f; }
    size_t arow0 = ((size_t)bh * NN + n0) * NN;
    size_t arow1 = ((size_t)bh * NN + n1) * NN;

#pragma unroll
    for (int t = 0; t < NTILE; t++) {
        __syncthreads();
#pragma unroll
        for (int r = 0; r < 8; r++) {
            int i  = tid + 256 * r;
            int mi = i >> 2;
            int d4 = (i & 3) << 2;
            float4 vv = *(const float4*)(vb + ((size_t)(t * TM + mi)) * DK + d4);
            *(float4*)(ts + mi * 20 + d4) = vv;
        }
        __syncthreads();
#pragma unroll
        for (int jj = 0; jj < SJ; jj++) {
            int lm = (jj << 5) + l;
            int m  = t * TM + lm;
            float p0 = s0[t * SJ + jj] * inv0;
            float p1 = s1[t * SJ + jj] * inv1;
            if (attnp) {
                attnp[arow0 + m] = p0;
                attnp[arow1 + m] = p1;
            }
            const float4* vr = (const float4*)(ts + lm * 20);
            float4 v0 = vr[0], v1 = vr[1], v2 = vr[2], v3 = vr[3];
            o0[0]  = fmaf(p0, v0.x, o0[0]);  o0[1]  = fmaf(p0, v0.y, o0[1]);
            o0[2]  = fmaf(p0, v0.z, o0[2]);  o0[3]  = fmaf(p0, v0.w, o0[3]);
            o0[4]  = fmaf(p0, v1.x, o0[4]);  o0[5]  = fmaf(p0, v1.y, o0[5]);
            o0[6]  = fmaf(p0, v1.z, o0[6]);  o0[7]  = fmaf(p0, v1.w, o0[7]);
            o0[8]  = fmaf(p0, v2.x, o0[8]);  o0[9]  = fmaf(p0, v2.y, o0[9]);
            o0[10] = fmaf(p0, v2.z, o0[10]); o0[11] = fmaf(p0, v2.w, o0[11]);
            o0[12] = fmaf(p0, v3.x, o0[12]); o0[13] = fmaf(p0, v3.y, o0[13]);
            o0[14] = fmaf(p0, v3.z, o0[14]); o0[15] = fmaf(p0, v3.w, o0[15]);

            o1[0]  = fmaf(p1, v0.x, o1[0]);  o1[1]  = fmaf(p1, v0.y, o1[1]);
            o1[2]  = fmaf(p1, v0.z, o1[2]);  o1[3]  = fmaf(p1, v0.w, o1[3]);
            o1[4]  = fmaf(p1, v1.x, o1[4]);  o1[5]  = fmaf(p1, v1.y, o1[5]);
            o1[6]  = fmaf(p1, v1.z, o1[6]);  o1[7]  = fmaf(p1, v1.w, o1[7]);
            o1[8]  = fmaf(p1, v2.x, o1[8]);  o1[9]  = fmaf(p1, v2.y, o1[9]);
            o1[10] = fmaf(p1, v2.z, o1[10]); o1[11] = fmaf(p1, v2.w, o1[11]);
            o1[12] = fmaf(p1, v3.x, o1[12]); o1[13] = fmaf(p1, v3.y, o1[13]);
            o1[14] = fmaf(p1, v3.z, o1[14]); o1[15] = fmaf(p1, v3.w, o1[15]);
        }
    }

    // warp butterfly reduce PV partials for both rows
#pragma unroll
    for (int off = 16; off; off >>= 1) {
#pragma unroll
        for (int d = 0; d < DK; d++) {
            o0[d] += __shfl_xor_sync(0xffffffffu, o0[d], off);
            o1[d] += __shfl_xor_sync(0xffffffffu, o1[d], off);
        }
    }

    // out layout: (b, n, dk, h) flattened -> out[(b*N+n)*128 + d*8 + h]
    if (outp) {
        if (l == 0) {
            float* ob = outp + ((size_t)b * NN + n0) * DOUT + h;
#pragma unroll
            for (int d = 0; d < DK; d++) ob[(size_t)d * H] = o0[d];
        } else if (l == 1) {
            float* ob = outp + ((size_t)b * NN + n1) * DOUT + h;
#pragma unroll
            for (int d = 0; d < DK; d++) ob[(size_t)d * H] = o1[d];
        }
    }
}

// ============================================================
extern "C" void kernel_launch(void* const* d_in, const int* in_sizes, int n_in,
                              void* d_out, int out_size) {
    const float* x   = (const float*)d_in[0];
    const int*   adj = (const int*)  d_in[1];
    const float* sp  = (const float*)d_in[2];
    const float* Wq  = (const float*)d_in[3];
    const float* bq  = (const float*)d_in[4];
    const float* Wk  = (const float*)d_in[5];
    const float* bk  = (const float*)d_in[6];
    const float* Wv  = (const float*)d_in[7];
    const float* bv  = (const float*)d_in[8];

    const long long OUT_ELEMS  = (long long)BS * NN * DOUT;              // 524288
    const long long ATTN_ELEMS = (long long)BS * H * NN * (long long)NN; // 67108864

    float* base  = (float*)d_out;
    float* outp  = nullptr;
    float* attnp = nullptr;
    long long osz = (long long)out_size;
    if (osz >= OUT_ELEMS + ATTN_ELEMS) { outp = base; attnp = base + OUT_ELEMS; }
    else if (osz == ATTN_ELEMS)        { attnp = base; }
    else                               { outp = base; }

    dim3 pgrid(BS * NN / PBM, 3);
    proj_kernel<<<pgrid, 256>>>(x, Wq, bq, Wk, bk, Wv, bv);

    dim3 agrid(NN / RT, H, BS);
    attn_kernel<<<agrid, 256>>>(sp, adj, outp, attnp);
}